// round 17
// baseline (speedup 1.0000x reference)
#include <cuda_runtime.h>
#include <cuda_bf16.h>
#include <cstdint>
#include <math.h>

#define NN 50000
#define NE 800000
#define FIN 512
#define HD1 64
#define HD2 128
#define NG 64
#define NC 10

// ---------------- scratch (device globals; zero-init at module load) -----------
// Persistent-state contract: k_final zeroes g_deg/g_poolA/g_poolH/g_cnt at the
// END of every call, so each call starts from the state it needs. First call
// relies on static zero-init. Same inputs -> same work -> same output.
__device__ __align__(16) float    g_buf1[(size_t)NN * 128]; // GEMM1 out [y_l|y_r]
__device__ __align__(16) float    g_h   [(size_t)NN * 64];  // layer-1 activations
__device__ __align__(16) unsigned g_B1t [128 * 512];        // tf32 [w1_l|w1_r]^T : [n][k]
__device__ int      g_deg [NN];
__device__ int      g_rowstart[NN + 1];
__device__ int      g_cursor[NN];
__device__ __align__(16) int g_csrsrc[NE];
__device__ float    g_poolA[NG * HD1];   // sum over graph of mean_h (neighbor mean)
__device__ float    g_poolH[NG * HD1];   // sum over graph of h
__device__ int      g_cnt [NG];
__device__ int      g_is64;              // 1 if edge_index/batch are int64

__device__ __forceinline__ unsigned f2tf32(float x) {
    unsigned r;
    asm("cvt.rna.tf32.f32 %0, %1;" : "=r"(r) : "f"(x));
    return r;
}
__device__ __forceinline__ unsigned u2tf32(unsigned ub) {
    unsigned r; float f = __uint_as_float(ub);
    asm("cvt.rna.tf32.f32 %0, %1;" : "=r"(r) : "f"(f));
    return r;
}
__device__ __forceinline__ void cp16(unsigned* dst_smem, const void* src) {
    unsigned d = (unsigned)__cvta_generic_to_shared(dst_smem);
    asm volatile("cp.async.cg.shared.global [%0], [%1], 16;" :: "r"(d), "l"(src) : "memory");
}
__device__ __forceinline__ void ldm4(const unsigned* p, unsigned& r0, unsigned& r1,
                                     unsigned& r2, unsigned& r3) {
    unsigned a = (unsigned)__cvta_generic_to_shared(p);
    asm volatile("ldmatrix.sync.aligned.m8n8.x4.shared.b16 {%0,%1,%2,%3}, [%4];"
                 : "=r"(r0), "=r"(r1), "=r"(r2), "=r"(r3) : "r"(a));
}
__device__ __forceinline__ int clampN(int v, int n) {
    return (v < 0) ? 0 : (v >= n ? n - 1 : v);
}

// ------- fused setup: dtype detect + pack B1t + deg histogram + cnt histogram --
// deg/cnt/pools arrive zeroed (see persistent-state contract above).
__global__ void k_setup(const float* __restrict__ wl1, const float* __restrict__ wr1,
                        const int* __restrict__ ei, const int* __restrict__ batch) {
    __shared__ int s_is64;
    if (threadIdx.x == 0) {                  // int64 LE => odd int32 words all 0
        int odd_or = 0;
#pragma unroll 8
        for (int q = 0; q < 256; q++) odd_or |= ei[2 * q + 1];
        s_is64 = (odd_or == 0) ? 1 : 0;
        if (blockIdx.x == 0) g_is64 = s_is64;
    }
    __syncthreads();
    const int is64 = s_is64;
    int i = blockIdx.x * 256 + threadIdx.x;

    if (i < 512 * 128) {                     // B1t[j][k] = ([w1_l|w1_r])(k,j), tf32
        int k = i >> 7, j = i & 127;
        float v = (j < 64) ? wl1[k * 64 + j] : wr1[k * 64 + (j - 64)];
        g_B1t[j * 512 + k] = f2tf32(v);
    }
    if (i < NN) {                            // graph-size histogram
        int b = clampN(is64 ? batch[2 * i] : batch[i], NG);
        atomicAdd(&g_cnt[b], 1);
    }
    // degree histogram, 4 edges/thread
    int e4 = i * 4;
    if (e4 < NE) {
        if (!is64) {
            int4 d = *(const int4*)(ei + NE + e4);
            atomicAdd(&g_deg[clampN(d.x, NN)], 1);
            atomicAdd(&g_deg[clampN(d.y, NN)], 1);
            atomicAdd(&g_deg[clampN(d.z, NN)], 1);
            atomicAdd(&g_deg[clampN(d.w, NN)], 1);
        } else {
            for (int e = e4; e < e4 + 4 && e < NE; e++)
                atomicAdd(&g_deg[clampN(ei[2 * (NE + e)], NN)], 1);
        }
    }
}

// ---------------- CSR scan + fill ----------------------------------------------
__global__ void k_scan() {
    __shared__ int sums[1024];
    const int t = threadIdx.x;
    const int chunk = (NN + 1023) >> 10;          // 49
    int beg = t * chunk, end = beg + chunk;
    if (end > NN) end = NN;
    if (beg > NN) beg = NN;
    int s = 0;
    for (int i = beg; i < end; i++) s += g_deg[i];
    sums[t] = s;
    __syncthreads();
    for (int off = 1; off < 1024; off <<= 1) {
        int v = (t >= off) ? sums[t - off] : 0;
        __syncthreads();
        sums[t] += v;
        __syncthreads();
    }
    int run = sums[t] - s;
    for (int i = beg; i < end; i++) {
        g_rowstart[i] = run;
        g_cursor[i]   = run;
        run += g_deg[i];
    }
    if (t == 1023) g_rowstart[NN] = sums[1023];
}

__global__ void k_fill(const int* __restrict__ ei) {
    int is64 = g_is64;
    int e4 = (blockIdx.x * 256 + threadIdx.x) * 4;
    if (e4 >= NE) return;
    if (!is64) {
        int4 s = *(const int4*)(ei + e4);
        int4 d = *(const int4*)(ei + NE + e4);
        int p;
        p = atomicAdd(&g_cursor[clampN(d.x, NN)], 1); if (p >= 0 && p < NE) g_csrsrc[p] = clampN(s.x, NN);
        p = atomicAdd(&g_cursor[clampN(d.y, NN)], 1); if (p >= 0 && p < NE) g_csrsrc[p] = clampN(s.y, NN);
        p = atomicAdd(&g_cursor[clampN(d.z, NN)], 1); if (p >= 0 && p < NE) g_csrsrc[p] = clampN(s.z, NN);
        p = atomicAdd(&g_cursor[clampN(d.w, NN)], 1); if (p >= 0 && p < NE) g_csrsrc[p] = clampN(s.w, NN);
    } else {
        for (int e = e4; e < e4 + 4 && e < NE; e++) {
            int s = clampN(ei[2 * e], NN);
            int d = clampN(ei[2 * (NE + e)], NN);
            int p = atomicAdd(&g_cursor[d], 1);
            if (p >= 0 && p < NE) g_csrsrc[p] = s;
        }
    }
}

// ---------------- tf32 GEMM: ldmatrix frags + cp.async double buffer -----------
// C[M,128] = A[M,512] @ Bt^T.  A row-major raw f32 (cvt after LDSM);
// Bt is [128 n][512] tf32.  BM=128, BN=128, BK=32, 256 threads, warp tile 32x64.
#define GEMM_SMEM_BYTES (4 * 128 * 36 * 4)   // 73728

__global__ __launch_bounds__(256, 2)
void gemm_lm(const float* __restrict__ A, const unsigned* __restrict__ Bt,
             float* __restrict__ C, int M) {
    constexpr int K = 512;
    extern __shared__ __align__(16) unsigned smem[];
    const int STR = 36, TBUF = 128 * 36;
    unsigned* As = smem;              // [2][128][36]
    unsigned* Bs = smem + 2 * TBUF;   // [2][128][36]

    const int tid = threadIdx.x;
    const int wid = tid >> 5, lane = tid & 31;
    const int g = lane >> 2, t = lane & 3;
    const int warpM = wid & 3, warpN = wid >> 2;
    const int rowBase = warpM * 32, colBase = warpN * 64;
    const int blockRow = blockIdx.x * 128;

    const int srow = tid >> 1, shalf = tid & 1;
    int agr = blockRow + srow; if (agr >= M) agr = M - 1;   // clamp; tail never stored
    const unsigned sDst = srow * STR + shalf * 16;
    const float*    aSrcBase = A  + (size_t)agr * K + shalf * 16;
    const unsigned* bSrcBase = Bt + (size_t)srow * K + shalf * 16;

    const int aRow = (lane & 7) + ((lane >> 3) & 1) * 8;
    const int aCol = ((lane >> 4) & 1) * 4;
    const int bRow = (lane & 7) + ((lane >> 4) & 1) * 8;
    const int bCol = ((lane >> 3) & 1) * 4;

    float acc[2][8][4];
#pragma unroll
    for (int mi = 0; mi < 2; mi++)
#pragma unroll
        for (int ni = 0; ni < 8; ni++)
#pragma unroll
            for (int r = 0; r < 4; r++) acc[mi][ni][r] = 0.f;

    constexpr int NT = K / 32;

    auto stage = [&](int kt, int buf) {
        unsigned* ad = As + buf * TBUF + sDst;
        const float* asrc = aSrcBase + kt;
#pragma unroll
        for (int j = 0; j < 4; j++) cp16(ad + j * 4, asrc + j * 4);
        unsigned* bd = Bs + buf * TBUF + sDst;
        const unsigned* bsrc = bSrcBase + kt;
#pragma unroll
        for (int j = 0; j < 4; j++) cp16(bd + j * 4, bsrc + j * 4);
        asm volatile("cp.async.commit_group;" ::: "memory");
    };

    stage(0, 0);

    int cur = 0;
    for (int ti = 0; ti < NT; ti++) {
        if (ti + 1 < NT) {
            stage((ti + 1) * 32, cur ^ 1);
            asm volatile("cp.async.wait_group 1;" ::: "memory");
        } else {
            asm volatile("cp.async.wait_group 0;" ::: "memory");
        }
        __syncthreads();

        const unsigned* Ab = As + cur * TBUF;
        const unsigned* Bb = Bs + cur * TBUF;
#pragma unroll
        for (int kk = 0; kk < 4; kk++) {
            const int k0 = kk * 8;
            unsigned a[2][4];
#pragma unroll
            for (int mi = 0; mi < 2; mi++) {
                ldm4(Ab + (rowBase + mi * 16 + aRow) * STR + k0 + aCol,
                     a[mi][0], a[mi][1], a[mi][2], a[mi][3]);
                a[mi][0] = u2tf32(a[mi][0]); a[mi][1] = u2tf32(a[mi][1]);
                a[mi][2] = u2tf32(a[mi][2]); a[mi][3] = u2tf32(a[mi][3]);
            }
            unsigned b[8][2];
#pragma unroll
            for (int nip = 0; nip < 4; nip++) {
                ldm4(Bb + (colBase + nip * 16 + bRow) * STR + k0 + bCol,
                     b[2 * nip][0], b[2 * nip][1], b[2 * nip + 1][0], b[2 * nip + 1][1]);
            }
#pragma unroll
            for (int mi = 0; mi < 2; mi++)
#pragma unroll
                for (int ni = 0; ni < 8; ni++)
                    asm volatile(
                        "mma.sync.aligned.m16n8k8.row.col.f32.tf32.tf32.f32 "
                        "{%0,%1,%2,%3}, {%4,%5,%6,%7}, {%8,%9}, {%0,%1,%2,%3};\n"
                        : "+f"(acc[mi][ni][0]), "+f"(acc[mi][ni][1]),
                          "+f"(acc[mi][ni][2]), "+f"(acc[mi][ni][3])
                        : "r"(a[mi][0]), "r"(a[mi][1]), "r"(a[mi][2]), "r"(a[mi][3]),
                          "r"(b[ni][0]), "r"(b[ni][1]));
        }
        cur ^= 1;
        __syncthreads();
    }

#pragma unroll
    for (int mi = 0; mi < 2; mi++) {
        int r0 = blockRow + rowBase + mi * 16 + g;
#pragma unroll
        for (int ni = 0; ni < 8; ni++) {
            int c = colBase + ni * 8 + 2 * t;
            if (r0 < M)
                *(float2*)(C + (size_t)r0 * 128 + c) =
                    make_float2(acc[mi][ni][0], acc[mi][ni][1]);
            if (r0 + 8 < M)
                *(float2*)(C + (size_t)(r0 + 8) * 128 + c) =
                    make_float2(acc[mi][ni][2], acc[mi][ni][3]);
        }
    }
}

// ------- layer-1 combine: h = relu(mean(agg y_l) + b1 + y_r); poolH += h -------
__global__ void k_agg1(const float* __restrict__ y, const float* __restrict__ b1,
                       const int* __restrict__ batch, float* __restrict__ h) {
    int node = blockIdx.x * 8 + (threadIdx.x >> 5);
    if (node >= NN) return;
    int lane = threadIdx.x & 31;
    int half = lane >> 4, fl = lane & 15;
    int beg = g_rowstart[node], end = g_rowstart[node + 1];
    float4 acc = make_float4(0.f, 0.f, 0.f, 0.f);
    for (int e = beg + half; e < end; e += 2) {
        int s = g_csrsrc[e];
        float4 v = *(const float4*)(y + (size_t)s * 128 + fl * 4);
        acc.x += v.x; acc.y += v.y; acc.z += v.z; acc.w += v.w;
    }
    acc.x += __shfl_xor_sync(0xffffffffu, acc.x, 16);
    acc.y += __shfl_xor_sync(0xffffffffu, acc.y, 16);
    acc.z += __shfl_xor_sync(0xffffffffu, acc.z, 16);
    acc.w += __shfl_xor_sync(0xffffffffu, acc.w, 16);
    if (half == 0) {
        float inv = 1.f / fmaxf((float)(end - beg), 1.f);
        float4 yr = *(const float4*)(y + (size_t)node * 128 + 64 + fl * 4);
        float4 bb = *(const float4*)(b1 + fl * 4);
        float4 o;
        o.x = fmaxf(acc.x * inv + bb.x + yr.x, 0.f);
        o.y = fmaxf(acc.y * inv + bb.y + yr.y, 0.f);
        o.z = fmaxf(acc.z * inv + bb.z + yr.z, 0.f);
        o.w = fmaxf(acc.w * inv + bb.w + yr.w, 0.f);
        *(float4*)(h + (size_t)node * 64 + fl * 4) = o;
        int b = clampN(g_is64 ? batch[2 * node] : batch[node], NG);
        float* ph = g_poolH + b * HD1 + fl * 4;
        atomicAdd(ph + 0, o.x); atomicAdd(ph + 1, o.y);
        atomicAdd(ph + 2, o.z); atomicAdd(ph + 3, o.w);
    }
}

// ------- layer-2 neighbor mean: poolA += mean(agg h)  (no per-node write) ------
__global__ void k_agg2(const float* __restrict__ h, const int* __restrict__ batch) {
    int node = blockIdx.x * 8 + (threadIdx.x >> 5);
    if (node >= NN) return;
    int lane = threadIdx.x & 31;
    int half = lane >> 4, fl = lane & 15;
    int beg = g_rowstart[node], end = g_rowstart[node + 1];
    float4 acc = make_float4(0.f, 0.f, 0.f, 0.f);
    for (int e = beg + half; e < end; e += 2) {
        int s = g_csrsrc[e];
        float4 v = *(const float4*)(h + (size_t)s * 64 + fl * 4);
        acc.x += v.x; acc.y += v.y; acc.z += v.z; acc.w += v.w;
    }
    acc.x += __shfl_xor_sync(0xffffffffu, acc.x, 16);
    acc.y += __shfl_xor_sync(0xffffffffu, acc.y, 16);
    acc.z += __shfl_xor_sync(0xffffffffu, acc.z, 16);
    acc.w += __shfl_xor_sync(0xffffffffu, acc.w, 16);
    if (half == 0) {
        float inv = 1.f / fmaxf((float)(end - beg), 1.f);
        int b = clampN(g_is64 ? batch[2 * node] : batch[node], NG);
        float* pa = g_poolA + b * HD1 + fl * 4;
        atomicAdd(pa + 0, acc.x * inv); atomicAdd(pa + 1, acc.y * inv);
        atomicAdd(pa + 2, acc.z * inv); atomicAdd(pa + 3, acc.w * inv);
    }
}

// ------- final: z128 = meanA@w2l + b2 + meanH@w2r; logits@wfc; log_softmax -----
// One block per graph. Also zeroes persistent state for the next call.
__global__ void k_final(const float* __restrict__ w2l, const float* __restrict__ b2,
                        const float* __restrict__ w2r,
                        const float* __restrict__ wfc, const float* __restrict__ bfc,
                        float* __restrict__ out) {
    __shared__ float zv[HD2];
    __shared__ float logits[NC];
    const int gi = blockIdx.x, c = threadIdx.x;   // c in [0,128)
    const int cn = g_cnt[gi];
    const float invc = (cn > 0) ? 1.f / (float)cn : 0.f;
    float z = (cn > 0) ? b2[c] : 0.f;
#pragma unroll 8
    for (int k = 0; k < HD1; k++) {
        z += (g_poolA[gi * HD1 + k] * invc) * w2l[k * HD2 + c]
           + (g_poolH[gi * HD1 + k] * invc) * w2r[k * HD2 + c];
    }
    zv[c] = z;
    __syncthreads();
    if (c < NC) {
        float l = bfc[c];
#pragma unroll 8
        for (int k = 0; k < HD2; k++) l += zv[k] * wfc[k * NC + c];
        logits[c] = l;
    }
    __syncthreads();
    if (c < NC) {
        float m = logits[0];
#pragma unroll
        for (int q = 1; q < NC; q++) m = fmaxf(m, logits[q]);
        float s = 0.f;
#pragma unroll
        for (int q = 0; q < NC; q++) s += expf(logits[q] - m);
        out[gi * NC + c] = logits[c] - (m + logf(s));
    }
    __syncthreads();
    // ---- reset persistent state for the next call ----
    if (c < HD1) { g_poolA[gi * HD1 + c] = 0.f; g_poolH[gi * HD1 + c] = 0.f; }
    if (c == HD1) g_cnt[gi] = 0;
    for (int i = gi * 128 + c; i < NN; i += NG * 128) g_deg[i] = 0;
}

// ---------------- launch -------------------------------------------------------
extern "C" void kernel_launch(void* const* d_in, const int* in_sizes, int n_in,
                              void* d_out, int out_size) {
    const float* x     = (const float*)d_in[0];
    const int*   ei    = (const int*)d_in[1];    // int32 OR int64 (runtime-detected)
    const int*   batch = (const int*)d_in[2];
    const float* w1l   = (const float*)d_in[3];
    const float* b1    = (const float*)d_in[4];
    const float* w1r   = (const float*)d_in[5];
    const float* w2l   = (const float*)d_in[6];
    const float* b2    = (const float*)d_in[7];
    const float* w2r   = (const float*)d_in[8];
    const float* wfc   = (const float*)d_in[9];
    const float* bfc   = (const float*)d_in[10];
    float* out = (float*)d_out;

    float *buf1, *hbuf;
    unsigned *B1t;
    cudaGetSymbolAddress((void**)&buf1, g_buf1);
    cudaGetSymbolAddress((void**)&hbuf, g_h);
    cudaGetSymbolAddress((void**)&B1t,  g_B1t);

    cudaFuncSetAttribute(gemm_lm, cudaFuncAttributeMaxDynamicSharedMemorySize,
                         GEMM_SMEM_BYTES);

    const int SETUP_BLOCKS = (NE / 4 + 255) / 256;   // 782: covers packs + hists
    k_setup<<<SETUP_BLOCKS, 256>>>(w1l, w1r, ei, batch);
    k_scan<<<1, 1024>>>();
    k_fill<<<(NE / 4 + 255) / 256, 256>>>(ei);

    gemm_lm<<<(NN + 127) / 128, 256, GEMM_SMEM_BYTES>>>(x, B1t, buf1, NN);
    k_agg1<<<(NN + 7) / 8, 256>>>(buf1, b1, batch, hbuf);
    k_agg2<<<(NN + 7) / 8, 256>>>(hbuf, batch);

    k_final<<<NG, 128>>>(w2l, b2, w2r, wfc, bfc, out);
}